// round 3
// baseline (speedup 1.0000x reference)
#include <cuda_runtime.h>

#define BATCH 8
#define NNODES 512
#define DIM 128
#define QHALF (BATCH * NNODES * (DIM / 4))   // 131072 float4 per output half

#define HEAD_BLOCKS_PER_BATCH 8
#define HEAD_BLOCKS (BATCH * HEAD_BLOCKS_PER_BATCH)           // 64
#define NF_BLOCKS (QHALF / 256)                               // 512
#define TOTAL_BLOCKS (HEAD_BLOCKS + NF_BLOCKS)                // 576
// each head block writes QHALF / HEAD_BLOCKS = 2048 float4 (8 per thread)
#define HB_F4 (QHALF / HEAD_BLOCKS)                           // 2048

__global__ void __launch_bounds__(256) gcn_fused_kernel(
    const float* __restrict__ x,      // [B, N, 2]
    const float* __restrict__ Wi,     // [2, D]
    const float* __restrict__ bi,     // [D]
    const float* __restrict__ W1,     // [D, D]
    const float* __restrict__ b1,     // [D]
    const float* __restrict__ W2,     // [D, D]
    const float* __restrict__ b2,     // [D]
    float* __restrict__ out)
{
    const int t = threadIdx.x;
    float4* out4 = (float4*)out;

    if (blockIdx.x >= HEAD_BLOCKS) {
        // ---------- node_feature half: out[B*N*D ..) = x @ W_init + b_init ----------
        const int idx = (blockIdx.x - HEAD_BLOCKS) * 256 + t;  // 0 .. QHALF-1
        const int b  = idx >> 14;                // N*D/4 = 16384
        const int n  = (idx >> 5) & (NNODES - 1);
        const int d4 = idx & 31;                 // D/4 = 32
        const float2 xv = ((const float2*)x)[b * NNODES + n];
        const float4 w0 = ((const float4*)Wi)[d4];
        const float4 w1 = ((const float4*)Wi)[32 + d4];
        const float4 bb = ((const float4*)bi)[d4];
        float4 r;
        r.x = fmaf(xv.x, w0.x, fmaf(xv.y, w1.x, bb.x));
        r.y = fmaf(xv.x, w0.y, fmaf(xv.y, w1.y, bb.y));
        r.z = fmaf(xv.x, w0.z, fmaf(xv.y, w1.z, bb.z));
        r.w = fmaf(xv.x, w0.w, fmaf(xv.y, w1.w, bb.w));
        out4[QHALF + idx] = r;
        return;
    }

    // ---------- head + broadcast half ----------
    const int hb  = blockIdx.x;
    const int b   = hb >> 3;                      // batch
    const int sub = hb & (HEAD_BLOCKS_PER_BATCH - 1);

    __shared__ float sv[DIM];       // vector being multiplied
    __shared__ float red[32];       // cross-warp reduction scratch
    __shared__ float lss[DIM];      // final log_softmax values

    const int lane = t & 31;
    const int wid  = t >> 5;

    // --- mean of x over 512 nodes (2 nodes per thread) ---
    const float2* xb = (const float2*)(x + (size_t)b * NNODES * 2);
    float2 v0 = xb[t];
    float2 v1 = xb[t + 256];
    float s0 = v0.x + v1.x;
    float s1 = v0.y + v1.y;
    #pragma unroll
    for (int off = 16; off > 0; off >>= 1) {
        s0 += __shfl_xor_sync(0xffffffffu, s0, off);
        s1 += __shfl_xor_sync(0xffffffffu, s1, off);
    }
    if (lane == 0) { red[wid] = s0; red[8 + wid] = s1; }
    __syncthreads();
    float m0, m1;
    {
        float a = red[0] + red[1] + red[2] + red[3] + red[4] + red[5] + red[6] + red[7];
        float c = red[8] + red[9] + red[10] + red[11] + red[12] + red[13] + red[14] + red[15];
        m0 = a * (1.0f / NNODES);
        m1 = c * (1.0f / NNODES);
    }
    __syncthreads();

    // --- mean node_feature ---
    if (t < DIM) {
        sv[t] = fmaf(m0, Wi[t], fmaf(m1, Wi[DIM + t], bi[t]));
    }
    __syncthreads();

    // --- conv1 matvec + relu (threads 0..127, 4 independent accumulators) ---
    float r1v = 0.f;
    if (t < DIM) {
        const float* w = W1 + t;
        float a0 = 0.f, a1 = 0.f, a2 = 0.f, a3 = 0.f;
        #pragma unroll
        for (int k = 0; k < DIM; k += 4) {
            a0 = fmaf(sv[k + 0], w[(k + 0) * DIM], a0);
            a1 = fmaf(sv[k + 1], w[(k + 1) * DIM], a1);
            a2 = fmaf(sv[k + 2], w[(k + 2) * DIM], a2);
            a3 = fmaf(sv[k + 3], w[(k + 3) * DIM], a3);
        }
        r1v = fmaxf(b1[t] + ((a0 + a1) + (a2 + a3)), 0.f);
    }
    __syncthreads();
    if (t < DIM) sv[t] = r1v;
    __syncthreads();

    // --- conv2 matvec ---
    float h = -3.402823466e+38f;   // -FLT_MAX for inactive lanes in max-reduce
    if (t < DIM) {
        const float* w = W2 + t;
        float a0 = 0.f, a1 = 0.f, a2 = 0.f, a3 = 0.f;
        #pragma unroll
        for (int k = 0; k < DIM; k += 4) {
            a0 = fmaf(sv[k + 0], w[(k + 0) * DIM], a0);
            a1 = fmaf(sv[k + 1], w[(k + 1) * DIM], a1);
            a2 = fmaf(sv[k + 2], w[(k + 2) * DIM], a2);
            a3 = fmaf(sv[k + 3], w[(k + 3) * DIM], a3);
        }
        h = b2[t] + ((a0 + a1) + (a2 + a3));
    }

    // --- log_softmax over DIM (threads 0..127 hold values; all threads sync) ---
    float m = h;
    #pragma unroll
    for (int off = 16; off > 0; off >>= 1)
        m = fmaxf(m, __shfl_xor_sync(0xffffffffu, m, off));
    if (lane == 0) red[wid] = m;    // warps 0..3 hold real maxima; 4..7 hold -FLT_MAX
    __syncthreads();
    const float mx = fmaxf(fmaxf(red[0], red[1]), fmaxf(red[2], red[3]));

    float e = (t < DIM) ? __expf(h - mx) : 0.f;
    float se = e;
    #pragma unroll
    for (int off = 16; off > 0; off >>= 1)
        se += __shfl_xor_sync(0xffffffffu, se, off);
    __syncthreads();                // red[] max-phase reads done
    if (lane == 0) red[wid] = se;
    __syncthreads();
    const float sum = red[0] + red[1] + red[2] + red[3];
    const float lse = __logf(sum);

    if (t < DIM) lss[t] = h - mx - lse;
    __syncthreads();

    // --- broadcast stores: this block's 2048-float4 slice ---
    const float4* ls4 = (const float4*)lss;   // 32 entries
    float4* dst = out4 + (size_t)b * (NNODES * DIM / 4) + sub * HB_F4;
    #pragma unroll
    for (int i = 0; i < 8; i++) {
        const int pos = t + 256 * i;
        dst[pos] = ls4[pos & 31];
    }
}

extern "C" void kernel_launch(void* const* d_in, const int* in_sizes, int n_in,
                              void* d_out, int out_size) {
    const float* x  = (const float*)d_in[0];
    const float* Wi = (const float*)d_in[1];
    const float* bi = (const float*)d_in[2];
    const float* W1 = (const float*)d_in[3];
    const float* b1 = (const float*)d_in[4];
    const float* W2 = (const float*)d_in[5];
    const float* b2 = (const float*)d_in[6];
    float* out = (float*)d_out;

    gcn_fused_kernel<<<TOTAL_BLOCKS, 256>>>(x, Wi, bi, W1, b1, W2, b2, out);
}

// round 4
// speedup vs baseline: 1.6918x; 1.6918x over previous
#include <cuda_runtime.h>

#define BATCH 8
#define NNODES 512
#define DIM 128
#define QHALF (BATCH * NNODES * (DIM / 4))   // 131072 float4 per output half

#define HEAD_BLOCKS_PER_BATCH 8
#define HEAD_BLOCKS (BATCH * HEAD_BLOCKS_PER_BATCH)           // 64
#define NF_BLOCKS (QHALF / 256)                               // 512
#define TOTAL_BLOCKS (HEAD_BLOCKS + NF_BLOCKS)                // 576
#define HB_F4 (QHALF / HEAD_BLOCKS)                           // 2048 float4 per head block

__global__ void __launch_bounds__(256) gcn_fused_kernel(
    const float* __restrict__ x,      // [B, N, 2]
    const float* __restrict__ Wi,     // [2, D]
    const float* __restrict__ bi,     // [D]
    const float* __restrict__ W1,     // [D, D]
    const float* __restrict__ b1,     // [D]
    const float* __restrict__ W2,     // [D, D]
    const float* __restrict__ b2,     // [D]
    float* __restrict__ out)
{
    const int t = threadIdx.x;
    float4* out4 = (float4*)out;

    if (blockIdx.x >= HEAD_BLOCKS) {
        // ---------- node_feature half: out[B*N*D ..) = x @ W_init + b_init ----------
        const int idx = (blockIdx.x - HEAD_BLOCKS) * 256 + t;  // 0 .. QHALF-1
        const int b  = idx >> 14;                // N*D/4 = 16384
        const int n  = (idx >> 5) & (NNODES - 1);
        const int d4 = idx & 31;                 // D/4 = 32
        const float2 xv = ((const float2*)x)[b * NNODES + n];
        const float4 w0 = ((const float4*)Wi)[d4];
        const float4 w1 = ((const float4*)Wi)[32 + d4];
        const float4 bb = ((const float4*)bi)[d4];
        float4 r;
        r.x = fmaf(xv.x, w0.x, fmaf(xv.y, w1.x, bb.x));
        r.y = fmaf(xv.x, w0.y, fmaf(xv.y, w1.y, bb.y));
        r.z = fmaf(xv.x, w0.z, fmaf(xv.y, w1.z, bb.z));
        r.w = fmaf(xv.x, w0.w, fmaf(xv.y, w1.w, bb.w));
        out4[QHALF + idx] = r;
        return;
    }

    // ---------- head + broadcast half ----------
    const int b   = blockIdx.x >> 3;                       // batch
    const int sub = blockIdx.x & (HEAD_BLOCKS_PER_BATCH - 1);
    const int lane = t & 31;
    const int w    = t >> 5;                               // warp 0..7

    __shared__ float sv[DIM];            // vector being multiplied
    __shared__ float part[8 * DIM];      // warp partials (4 KB), also reduce scratch
    __shared__ float lss[DIM];           // final log_softmax values

    // --- mean of x over 512 nodes (2 nodes per thread) ---
    const float2* xb = (const float2*)(x + (size_t)b * NNODES * 2);
    float2 v0 = xb[t];
    float2 v1 = xb[t + 256];
    float s0 = v0.x + v1.x;
    float s1 = v0.y + v1.y;
    #pragma unroll
    for (int off = 16; off > 0; off >>= 1) {
        s0 += __shfl_xor_sync(0xffffffffu, s0, off);
        s1 += __shfl_xor_sync(0xffffffffu, s1, off);
    }
    if (lane == 0) { part[w] = s0; part[8 + w] = s1; }
    __syncthreads();
    const float m0 = (part[0] + part[1] + part[2] + part[3] +
                      part[4] + part[5] + part[6] + part[7]) * (1.0f / NNODES);
    const float m1 = (part[8] + part[9] + part[10] + part[11] +
                      part[12] + part[13] + part[14] + part[15]) * (1.0f / NNODES);
    __syncthreads();

    // --- mean node_feature ---
    if (t < DIM) sv[t] = fmaf(m0, Wi[t], fmaf(m1, Wi[DIM + t], bi[t]));
    __syncthreads();

    // ===== conv1: warp-split-k matvec, acc = mean_nf @ W1 =====
    {
        const float4* W4 = (const float4*)W1;   // row k at index k*32
        float4 a = make_float4(0.f, 0.f, 0.f, 0.f);
        #pragma unroll
        for (int kk = 0; kk < 16; kk++) {
            const int k = w * 16 + kk;
            const float s = sv[k];
            const float4 wv = W4[k * 32 + lane];
            a.x = fmaf(s, wv.x, a.x);
            a.y = fmaf(s, wv.y, a.y);
            a.z = fmaf(s, wv.z, a.z);
            a.w = fmaf(s, wv.w, a.w);
        }
        ((float4*)part)[w * 32 + lane] = a;
    }
    __syncthreads();
    float r1v = 0.f;
    if (t < DIM) {
        float s = b1[t];
        #pragma unroll
        for (int ww = 0; ww < 8; ww++) s += part[ww * DIM + t];
        r1v = fmaxf(s, 0.f);
    }
    __syncthreads();
    if (t < DIM) sv[t] = r1v;
    __syncthreads();

    // ===== conv2: warp-split-k matvec, h = r1 @ W2 =====
    {
        const float4* W4 = (const float4*)W2;
        float4 a = make_float4(0.f, 0.f, 0.f, 0.f);
        #pragma unroll
        for (int kk = 0; kk < 16; kk++) {
            const int k = w * 16 + kk;
            const float s = sv[k];
            const float4 wv = W4[k * 32 + lane];
            a.x = fmaf(s, wv.x, a.x);
            a.y = fmaf(s, wv.y, a.y);
            a.z = fmaf(s, wv.z, a.z);
            a.w = fmaf(s, wv.w, a.w);
        }
        ((float4*)part)[w * 32 + lane] = a;
    }
    __syncthreads();
    float h = -3.402823466e+38f;   // -FLT_MAX for inactive lanes in max-reduce
    if (t < DIM) {
        float s = b2[t];
        #pragma unroll
        for (int ww = 0; ww < 8; ww++) s += part[ww * DIM + t];
        h = s;
    }
    __syncthreads();

    // --- log_softmax over DIM (threads 0..127 hold values) ---
    float m = h;
    #pragma unroll
    for (int off = 16; off > 0; off >>= 1)
        m = fmaxf(m, __shfl_xor_sync(0xffffffffu, m, off));
    if (lane == 0) part[w] = m;    // warps 0..3 real maxima; 4..7 = -FLT_MAX
    __syncthreads();
    const float mx = fmaxf(fmaxf(part[0], part[1]), fmaxf(part[2], part[3]));

    float e = (t < DIM) ? __expf(h - mx) : 0.f;
    float se = e;
    #pragma unroll
    for (int off = 16; off > 0; off >>= 1)
        se += __shfl_xor_sync(0xffffffffu, se, off);
    __syncthreads();
    if (lane == 0) part[w] = se;
    __syncthreads();
    const float lse = __logf(part[0] + part[1] + part[2] + part[3]);

    if (t < DIM) lss[t] = h - mx - lse;
    __syncthreads();

    // --- broadcast stores: this block's 2048-float4 slice ---
    const float4* ls4 = (const float4*)lss;   // 32 entries
    float4* dst = out4 + (size_t)b * (NNODES * DIM / 4) + sub * HB_F4;
    #pragma unroll
    for (int i = 0; i < 8; i++) {
        const int pos = t + 256 * i;
        dst[pos] = ls4[pos & 31];
    }
}

extern "C" void kernel_launch(void* const* d_in, const int* in_sizes, int n_in,
                              void* d_out, int out_size) {
    const float* x  = (const float*)d_in[0];
    const float* Wi = (const float*)d_in[1];
    const float* bi = (const float*)d_in[2];
    const float* W1 = (const float*)d_in[3];
    const float* b1 = (const float*)d_in[4];
    const float* W2 = (const float*)d_in[5];
    const float* b2 = (const float*)d_in[6];
    float* out = (float*)d_out;

    gcn_fused_kernel<<<TOTAL_BLOCKS, 256>>>(x, Wi, bi, W1, b1, W2, b2, out);
}